// round 16
// baseline (speedup 1.0000x reference)
#include <cuda_runtime.h>
#include <cuda_fp16.h>
#include <math.h>
#include <stdint.h>

#define SEQ   4096
#define MODEL 2048
#define NH    16
#define HD    128
#define QKV_N (3*MODEL)
#define KB_MODEL (MODEL/16)   // 128

// Scratch (__device__ globals: allocation-free rule)
__device__ uint4  g_xf [(size_t)(SEQ/16)   * KB_MODEL * 32];  // x    A-frags
__device__ uint4  g_waf[(size_t)(QKV_N/16) * KB_MODEL * 32];  // w_attn B-frags
__device__ uint4  g_wpf[(size_t)(MODEL/16) * KB_MODEL * 32];  // w_proj B-frags
__device__ uint4  g_zf [(size_t)(SEQ/16)   * KB_MODEL * 32];  // z    A-frags
__device__ __half g_hidden[(size_t)SEQ * QKV_N];              // QKV out (row layout)

__device__ __forceinline__ uint32_t pack_h2(float a, float b) {
    __half2 h = __floats2half2_rn(a, b);
    return reinterpret_cast<uint32_t&>(h);
}
__device__ __forceinline__ void mma_f16(float* c, const uint32_t* a,
                                        uint32_t b0, uint32_t b1) {
    asm volatile(
        "mma.sync.aligned.m16n8k16.row.col.f32.f16.f16.f32 "
        "{%0,%1,%2,%3}, {%4,%5,%6,%7}, {%8,%9}, {%0,%1,%2,%3};\n"
        : "+f"(c[0]), "+f"(c[1]), "+f"(c[2]), "+f"(c[3])
        : "r"(a[0]), "r"(a[1]), "r"(a[2]), "r"(a[3]), "r"(b0), "r"(b1));
}
__device__ __forceinline__ void ldsm4_t(uint32_t* r, uint32_t addr) {
    asm volatile("ldmatrix.sync.aligned.m8n8.x4.trans.shared.b16 {%0,%1,%2,%3}, [%4];"
        : "=r"(r[0]), "=r"(r[1]), "=r"(r[2]), "=r"(r[3]) : "r"(addr));
}
__device__ __forceinline__ void lds128(uint4& v, uint32_t addr) {
    asm volatile("ld.shared.v4.u32 {%0,%1,%2,%3}, [%4];"
        : "=r"(v.x), "=r"(v.y), "=r"(v.z), "=r"(v.w) : "r"(addr));
}
__device__ __forceinline__ void cp16(uint32_t dst, const void* src) {
    asm volatile("cp.async.cg.shared.global [%0], [%1], 16;\n" :: "r"(dst), "l"(src));
}
__device__ __forceinline__ void cp_commit() { asm volatile("cp.async.commit_group;\n"); }
template<int N> __device__ __forceinline__ void cp_wait() {
    asm volatile("cp.async.wait_group %0;\n" :: "n"(N));
}
__device__ __forceinline__ uint32_t smem_u32(const void* p) {
    uint32_t a;
    asm("{ .reg .u64 t; cvta.to.shared.u64 t, %1; cvt.u32.u64 %0, t; }"
        : "=r"(a) : "l"(p));
    return a;
}

// ---------------------------------------------------------------------------
// Prep: pack x (fp32 [SEQ][MODEL]) into A-fragment layout.
// ---------------------------------------------------------------------------
__global__ void pack_a(const float* __restrict__ x, uint4* __restrict__ out) {
    __shared__ float sA[16][132];
    int cb = blockIdx.x;
    int mb = blockIdx.y;
    int tid = threadIdx.x;
    #pragma unroll
    for (int i = 0; i < 8; i++) {
        int id = tid + 256*i;
        int r = id >> 7, c = id & 127;
        sA[r][c] = x[(size_t)(mb*16 + r)*MODEL + cb*128 + c];
    }
    __syncthreads();
    int t = tid >> 5, lane = tid & 31, ra = lane >> 2, kq = lane & 3;
    int c0 = t*16;
    uint4 v;
    v.x = pack_h2(sA[ra][c0 + 2*kq],       sA[ra][c0 + 2*kq + 1]);
    v.y = pack_h2(sA[ra+8][c0 + 2*kq],     sA[ra+8][c0 + 2*kq + 1]);
    v.z = pack_h2(sA[ra][c0 + 8 + 2*kq],   sA[ra][c0 + 9 + 2*kq]);
    v.w = pack_h2(sA[ra+8][c0 + 8 + 2*kq], sA[ra+8][c0 + 9 + 2*kq]);
    out[((size_t)mb*KB_MODEL + cb*8 + t)*32 + lane] = v;
}

// ---------------------------------------------------------------------------
// Prep: pack weight w (fp32 [K][N]) into B-fragment layout (implicit transpose).
// ---------------------------------------------------------------------------
__global__ void pack_b(const float* __restrict__ w, uint4* __restrict__ out,
                       int Ncols, int Krows) {
    __shared__ float tile[32][33];
    int n0c = blockIdx.x * 32, k0 = blockIdx.y * 32;
    int tx = threadIdx.x, ty = threadIdx.y;
    #pragma unroll
    for (int i = 0; i < 32; i += 8)
        tile[ty + i][tx] = w[(size_t)(k0 + ty + i)*Ncols + n0c + tx];
    __syncthreads();
    int tid = ty*32 + tx;
    int sub = tid >> 5;
    if (sub < 4) {
        int nbl = sub & 1, kbl = sub >> 1;
        int lane = tid & 31, ra = lane >> 2, kq = lane & 3;
        int kk0 = kbl*16, nn0 = nbl*16;
        uint4 v;
        v.x = pack_h2(tile[kk0 + 2*kq][nn0 + ra],       tile[kk0 + 2*kq + 1][nn0 + ra]);
        v.y = pack_h2(tile[kk0 + 8 + 2*kq][nn0 + ra],   tile[kk0 + 9 + 2*kq][nn0 + ra]);
        v.z = pack_h2(tile[kk0 + 2*kq][nn0 + 8 + ra],   tile[kk0 + 2*kq + 1][nn0 + 8 + ra]);
        v.w = pack_h2(tile[kk0 + 8 + 2*kq][nn0 + 8 + ra], tile[kk0 + 9 + 2*kq][nn0 + 8 + ra]);
        int nb_g = (n0c >> 4) + nbl;
        int kb_g = (k0 >> 4) + kbl;
        out[((size_t)nb_g*(Krows >> 4) + kb_g)*32 + lane] = v;
    }
}

// ---------------------------------------------------------------------------
// fp16 GEMM on pre-packed fragments. 128x128 tile, BK=32/stage, GS=6 ring,
// TWO stages per barrier. Stage indices via wrap counters (no % 6 division).
// ---------------------------------------------------------------------------
#define TGS 6
#define STAGE_BYTES 16384
#define A_BYTES 8192
#define GEMM_SMEM (TGS*STAGE_BYTES)  // 96 KB

template<bool OUT_HALF>
__global__ __launch_bounds__(256, 2) void gemm_f16(
    const uint4* __restrict__ Af, const uint4* __restrict__ Bf,
    const float* __restrict__ bias, void* __restrict__ Cv,
    int N, int KB)
{
    extern __shared__ char gsm[];
    const int tid  = threadIdx.x;
    const int lane = tid & 31;
    const int warp = tid >> 5;
    const int kq   = lane & 3;
    const int mbw = (warp >> 2) * 4;
    const int nbw = (warp & 3) * 2;
    const int n0  = (warp & 3) * 32;
    const int mb0 = blockIdx.y * 8, nb0 = blockIdx.x * 8;
    const int row0 = blockIdx.y * 128, col0 = blockIdx.x * 128;

    uint32_t asS = (uint32_t)__cvta_generic_to_shared(gsm);
    const uint32_t aBase = (uint32_t)((mbw*2)*32 + lane) * 16u;
    const uint32_t bBase = (uint32_t)A_BYTES + (uint32_t)((nbw*2)*32 + lane) * 16u;
    const int niter = KB >> 1;

    // issue chunk t into explicit stage slot (no modulo)
    auto issue = [&](int t, int stage) {
        uint32_t sb = asS + (uint32_t)stage * STAGE_BYTES;
        #pragma unroll
        for (int j = 0; j < 2; j++) {
            int c = tid + 256*j;
            int bl = c >> 6, kkb = (c >> 5) & 1, ln = c & 31;
            cp16(sb + (uint32_t)c*16u,
                 Af + ((size_t)(mb0 + bl)*KB + 2*t + kkb)*32 + ln);
            cp16(sb + A_BYTES + (uint32_t)c*16u,
                 Bf + ((size_t)(nb0 + bl)*KB + 2*t + kkb)*32 + ln);
        }
        cp_commit();
    };

    #pragma unroll
    for (int s = 0; s < 4; s++) issue(s, s);

    float c[4][4][4];
    #pragma unroll
    for (int mi = 0; mi < 4; mi++)
        #pragma unroll
        for (int ni = 0; ni < 4; ni++)
            #pragma unroll
            for (int r = 0; r < 4; r++) c[mi][ni][r] = 0.f;

    int st_cur = 0;   // stage of chunk s
    int st_pre = 4;   // stage of chunk s+4
    const int npairs = niter >> 1;
    for (int p = 0; p < npairs; p++) {
        cp_wait<2>();
        __syncthreads();

        #pragma unroll
        for (int h2 = 0; h2 < 2; h2++) {
            int s = 2*p + h2;
            uint32_t sb = asS + (uint32_t)st_cur * STAGE_BYTES;
            st_cur = (st_cur == TGS-1) ? 0 : st_cur + 1;

            uint4 af[2][4];
            uint4 bf[2][2];
            #pragma unroll
            for (int kk = 0; kk < 2; kk++) {
                #pragma unroll
                for (int mi = 0; mi < 4; mi++)
                    lds128(af[kk][mi], sb + aBase + (uint32_t)(mi*2 + kk)*32u*16u);
                #pragma unroll
                for (int nbi = 0; nbi < 2; nbi++)
                    lds128(bf[kk][nbi], sb + bBase + (uint32_t)(nbi*2 + kk)*32u*16u);
            }

            if (s + 4 < niter) {
                issue(s + 4, st_pre);
                st_pre = (st_pre == TGS-1) ? 0 : st_pre + 1;
            } else cp_commit();

            #pragma unroll
            for (int kk = 0; kk < 2; kk++)
                #pragma unroll
                for (int nbi = 0; nbi < 2; nbi++) {
                    #pragma unroll
                    for (int mi = 0; mi < 4; mi++)
                        mma_f16(c[mi][2*nbi], (const uint32_t*)&af[kk][mi],
                                bf[kk][nbi].x, bf[kk][nbi].y);
                    #pragma unroll
                    for (int mi = 0; mi < 4; mi++)
                        mma_f16(c[mi][2*nbi+1], (const uint32_t*)&af[kk][mi],
                                bf[kk][nbi].z, bf[kk][nbi].w);
                }
        }
    }

    const int ra = lane >> 2;
    #pragma unroll
    for (int ni = 0; ni < 4; ni++) {
        int cc = col0 + n0 + ni*8 + 2*kq;
        float2 bb = *(const float2*)(bias + cc);
        #pragma unroll
        for (int mi = 0; mi < 4; mi++) {
            int r = row0 + mbw*16 + mi*16 + ra;
            float o0 = c[mi][ni][0] + bb.x, o1 = c[mi][ni][1] + bb.y;
            float o2 = c[mi][ni][2] + bb.x, o3 = c[mi][ni][3] + bb.y;
            if (OUT_HALF) {
                uint32_t* C32 = (uint32_t*)Cv;
                C32[(size_t)r * (N>>1) + (cc>>1)]       = pack_h2(o0, o1);
                C32[(size_t)(r + 8) * (N>>1) + (cc>>1)] = pack_h2(o2, o3);
            } else {
                float* C = (float*)Cv;
                *(float2*)(C + (size_t)r * N + cc)       = make_float2(o0, o1);
                *(float2*)(C + (size_t)(r + 8) * N + cc) = make_float2(o2, o3);
            }
        }
    }
}

// ---------------------------------------------------------------------------
// fp16 flash attention (causal). P stays ENTIRELY in registers: the PV
// A-fragment layout coincides with the S accumulator layout, so the smem
// P round-trip (16 STS + 16 LDS + syncwarp per tile) is deleted.
// ---------------------------------------------------------------------------
#define KS 68
#define VS 68
#define FL_SMEM ((2*64*KS + 2*64*VS)*4)   // 69.6 KB

__global__ __launch_bounds__(256, 1) void flash_f16(
    const __half* __restrict__ hidden, uint4* __restrict__ zf)
{
    extern __shared__ uint32_t sm[];
    uint32_t* Ks = sm;
    uint32_t* Vs = Ks + 2*64*KS;

    const uint32_t* hid32 = (const uint32_t*)hidden;
    const int Qw = QKV_N >> 1;

    const int h    = blockIdx.y;
    const int qb   = (int)(gridDim.x - 1) - (int)blockIdx.x;
    const int tid  = threadIdx.x;
    const int lane = tid & 31;
    const int warp = tid >> 5;
    const int m0   = warp * 16;
    const int ra   = lane >> 2;
    const int kq   = lane & 3;
    const float scale = 0.08838834764831845f;

    uint32_t asK = smem_u32(Ks);
    uint32_t asV = smem_u32(Vs);
    const int hoff = (MODEL >> 1) + (h*HD >> 1);

    auto load_tile = [&](int t) {
        uint32_t kb_ = asK + (uint32_t)(t & 1) * 64u*KS*4u;
        uint32_t vb_ = asV + (uint32_t)(t & 1) * 64u*VS*4u;
        #pragma unroll
        for (int i = 0; i < 4; i++) {
            int idx = tid + 256*i;
            int r = idx >> 4, c = idx & 15;
            const uint32_t* kp = hid32 + (size_t)(t*64 + r) * Qw + hoff + c*4;
            cp16(kb_ + (uint32_t)(r*KS + c*4)*4u, kp);
            cp16(vb_ + (uint32_t)(r*VS + c*4)*4u, kp + (MODEL >> 1));
        }
        cp_commit();
    };

    uint32_t qf[8][4];
    {
        const uint32_t* qp0 = hid32 + (size_t)(qb*128 + m0 + ra) * Qw + (h*HD >> 1);
        const uint32_t* qp1 = qp0 + (size_t)8 * Qw;
        #pragma unroll
        for (int i = 0; i < 8; i++) {
            qf[i][0] = qp0[i*8 + kq];
            qf[i][1] = qp1[i*8 + kq];
            qf[i][2] = qp0[i*8 + kq + 4];
            qf[i][3] = qp1[i*8 + kq + 4];
        }
    }

    float m_a = -1e30f, m_b = -1e30f, l_a = 0.f, l_b = 0.f;
    float o[16][4];
    #pragma unroll
    for (int ni = 0; ni < 16; ni++)
        o[ni][0] = o[ni][1] = o[ni][2] = o[ni][3] = 0.f;

    const int qr_a = qb*128 + m0 + ra;
    const int nkb  = 2*qb + 2;

    load_tile(0);
    load_tile(1);

    for (int kb = 0; kb < nkb; kb++) {
        cp_wait<1>();
        __syncthreads();

        const uint32_t* Kb = Ks + (kb & 1)*64*KS;
        uint32_t vb_byte = asV + (uint32_t)(kb & 1)*64u*VS*4u;

        // ---- S = Q @ K^T ----
        float s[8][4];
        #pragma unroll
        for (int n = 0; n < 8; n++) s[n][0] = s[n][1] = s[n][2] = s[n][3] = 0.f;

        #pragma unroll
        for (int i = 0; i < 8; i++) {
            #pragma unroll
            for (int n = 0; n < 8; n++) {
                const uint32_t* kp2 = Kb + (n*8 + ra)*KS + i*8 + kq;
                mma_f16(s[n], qf[i], kp2[0], kp2[4]);
            }
        }

        #pragma unroll
        for (int n = 0; n < 8; n++) {
            s[n][0] *= scale; s[n][1] *= scale;
            s[n][2] *= scale; s[n][3] *= scale;
        }

        if (kb >= 2*qb) {
            #pragma unroll
            for (int n = 0; n < 8; n++) {
                int col = kb*64 + n*8 + 2*kq;
                if (col     > qr_a)     s[n][0] = -1e30f;
                if (col + 1 > qr_a)     s[n][1] = -1e30f;
                if (col     > qr_a + 8) s[n][2] = -1e30f;
                if (col + 1 > qr_a + 8) s[n][3] = -1e30f;
            }
        }

        // ---- online softmax; P packed directly into registers ----
        float mxa = -1e30f, mxb = -1e30f;
        #pragma unroll
        for (int n = 0; n < 8; n++) {
            mxa = fmaxf(mxa, fmaxf(s[n][0], s[n][1]));
            mxb = fmaxf(mxb, fmaxf(s[n][2], s[n][3]));
        }
        mxa = fmaxf(mxa, __shfl_xor_sync(0xffffffffu, mxa, 1));
        mxa = fmaxf(mxa, __shfl_xor_sync(0xffffffffu, mxa, 2));
        mxb = fmaxf(mxb, __shfl_xor_sync(0xffffffffu, mxb, 1));
        mxb = fmaxf(mxb, __shfl_xor_sync(0xffffffffu, mxb, 2));

        float mna = fmaxf(m_a, mxa), mnb = fmaxf(m_b, mxb);
        float alpha_a = __expf(m_a - mna), alpha_b = __expf(m_b - mnb);
        float suma = 0.f, sumb = 0.f;
        uint32_t ph[8][2];   // ph[n][0] = rows ra pair, ph[n][1] = rows ra+8 pair
        #pragma unroll
        for (int n = 0; n < 8; n++) {
            float p0 = __expf(s[n][0] - mna), p1 = __expf(s[n][1] - mna);
            float p2 = __expf(s[n][2] - mnb), p3 = __expf(s[n][3] - mnb);
            suma += p0 + p1; sumb += p2 + p3;
            ph[n][0] = pack_h2(p0, p1);
            ph[n][1] = pack_h2(p2, p3);
        }
        suma += __shfl_xor_sync(0xffffffffu, suma, 1);
        suma += __shfl_xor_sync(0xffffffffu, suma, 2);
        sumb += __shfl_xor_sync(0xffffffffu, sumb, 1);
        sumb += __shfl_xor_sync(0xffffffffu, sumb, 2);
        l_a = l_a * alpha_a + suma;
        l_b = l_b * alpha_b + sumb;
        m_a = mna; m_b = mnb;
        #pragma unroll
        for (int ni = 0; ni < 16; ni++) {
            o[ni][0] *= alpha_a; o[ni][1] *= alpha_a;
            o[ni][2] *= alpha_b; o[ni][3] *= alpha_b;
        }

        // ---- O += P @ V  (A-frags from registers; V via ldmatrix.trans) ----
        const int g  = lane >> 3;
        const int rr = lane & 7;
        #pragma unroll
        for (int s4 = 0; s4 < 4; s4++) {
            uint32_t a[4] = { ph[2*s4][0], ph[2*s4][1],
                              ph[2*s4+1][0], ph[2*s4+1][1] };
            #pragma unroll
            for (int nn = 0; nn < 8; nn++) {
                uint32_t bfv[4];
                uint32_t addr = vb_byte +
                    (uint32_t)((s4*16 + (g & 1)*8 + rr)*VS + nn*8 + (g >> 1)*4) * 4u;
                ldsm4_t(bfv, addr);
                mma_f16(o[2*nn],     a, bfv[0], bfv[1]);
                mma_f16(o[2*nn + 1], a, bfv[2], bfv[3]);
            }
        }

        __syncthreads();
        if (kb + 2 < nkb) load_tile(kb + 2);
        else              cp_commit();
    }

    // ---- normalize + write z in A-fragment layout (proj GEMM fast path) ----
    float inva = 1.f / l_a, invb = 1.f / l_b;
    int mb_g = qb*8 + warp;
    #pragma unroll
    for (int j = 0; j < 8; j++) {
        int kb_g = h*8 + j;
        uint4 v;
        v.x = pack_h2(o[2*j][0]*inva,   o[2*j][1]*inva);
        v.y = pack_h2(o[2*j][2]*invb,   o[2*j][3]*invb);
        v.z = pack_h2(o[2*j+1][0]*inva, o[2*j+1][1]*inva);
        v.w = pack_h2(o[2*j+1][2]*invb, o[2*j+1][3]*invb);
        zf[((size_t)mb_g*KB_MODEL + kb_g)*32 + lane] = v;
    }
}

// ---------------------------------------------------------------------------
extern "C" void kernel_launch(void* const* d_in, const int* in_sizes, int n_in,
                              void* d_out, int out_size)
{
    const float* x      = (const float*)d_in[0];
    const float* w_attn = (const float*)d_in[1];
    const float* b_attn = (const float*)d_in[2];
    const float* w_proj = (const float*)d_in[3];
    const float* b_proj = (const float*)d_in[4];
    float* out = (float*)d_out;

    uint4 *xf, *waf, *wpf, *zf;
    __half* hid;
    cudaGetSymbolAddress((void**)&xf,  g_xf);
    cudaGetSymbolAddress((void**)&waf, g_waf);
    cudaGetSymbolAddress((void**)&wpf, g_wpf);
    cudaGetSymbolAddress((void**)&zf,  g_zf);
    cudaGetSymbolAddress((void**)&hid, g_hidden);

    cudaFuncSetAttribute(gemm_f16<true>,
                         cudaFuncAttributeMaxDynamicSharedMemorySize, GEMM_SMEM);
    cudaFuncSetAttribute(gemm_f16<false>,
                         cudaFuncAttributeMaxDynamicSharedMemorySize, GEMM_SMEM);
    cudaFuncSetAttribute(flash_f16,
                         cudaFuncAttributeMaxDynamicSharedMemorySize, FL_SMEM);

    // 0) prep: pack x into A-frags; weights into B-frags (implicit transpose)
    pack_a<<<dim3(MODEL/128, SEQ/16), 256>>>(x, xf);
    pack_b<<<dim3(QKV_N/32, MODEL/32), dim3(32, 8)>>>(w_attn, waf, QKV_N, MODEL);
    pack_b<<<dim3(MODEL/32, MODEL/32), dim3(32, 8)>>>(w_proj, wpf, MODEL, MODEL);

    // 1) QKV projection (fp16 row-layout out feeds flash)
    gemm_f16<true><<<dim3(QKV_N/128, SEQ/128), 256, GEMM_SMEM>>>(
        xf, waf, b_attn, hid, QKV_N, KB_MODEL);

    // 2) causal multi-head attention (writes z in A-frag layout)
    flash_f16<<<dim3(SEQ/128, NH), 256, FL_SMEM>>>(hid, zf);

    // 3) output projection (fp32 out)
    gemm_f16<false><<<dim3(MODEL/128, SEQ/128), 256, GEMM_SMEM>>>(
        zf, wpf, b_proj, out, MODEL, KB_MODEL);
}